// round 1
// baseline (speedup 1.0000x reference)
#include <cuda_runtime.h>
#include <cuda_bf16.h>
#include <math.h>

// Shapes (fixed by the problem):
// x: (100, 512, 16, 16) fp32  -> per sample: 512 channels x 256 pixels
// W: (512, 512) fp32 (outC, inC), b: (512,) zeros
// out: (75, 5) fp32
//
// Pipeline:
//  K1: logits[b][o][p] = sum_c x[b][c][p] * W[o][c] + bias[o]   (GEMM, 13.4 GF)
//  K2: per-sample max + 1/sum(exp) over 131072 logits
//  K3: prototypes s[way][c] = mean over (5 shots x 256 p) of x*mask
//  K4: per query (75) per pixel (256): cosine sim vs 5 protos, softmax(10*s), mean over pixels

#define NSAMP 100
#define C 512
#define P 256           // 16*16
#define ELEMS (C*P)     // 131072 per sample
#define WAY 5
#define SHOT 5
#define NQ 75

__device__ float g_logits[NSAMP * ELEMS];   // 52 MB scratch
__device__ float g_max[NSAMP];
__device__ float g_invsum[NSAMP];
__device__ float g_proto[WAY * C];

// ---------------------------------------------------------------------------
// K1: per-pixel 1x1 conv as GEMM. Block computes a 128(o) x 128(p) output tile
// for one sample b. K-loop over c in chunks of 16. 256 threads, 8x8 per thread.
// ---------------------------------------------------------------------------
__global__ __launch_bounds__(256) void gemm_kernel(
    const float* __restrict__ x, const float* __restrict__ W,
    const float* __restrict__ bias)
{
    const int b  = blockIdx.z;
    const int o0 = blockIdx.y * 128;
    const int p0 = blockIdx.x * 128;

    __shared__ float As[16][128];   // [c_local][o_local]  (W chunk, transposed)
    __shared__ float Bs[16][128];   // [c_local][p_local]  (x chunk)

    const float* xb = x + (size_t)b * ELEMS;

    const int tid = threadIdx.x;
    const int ty = tid >> 4;        // 0..15 -> o sub-tile
    const int tx = tid & 15;        // 0..15 -> p sub-tile

    float acc[8][8];
    #pragma unroll
    for (int i = 0; i < 8; i++)
        #pragma unroll
        for (int j = 0; j < 8; j++) acc[i][j] = 0.f;

    for (int c0 = 0; c0 < C; c0 += 16) {
        // Load W chunk: 128 rows(o) x 16 cols(c); each thread 8 consecutive cols.
        {
            const int row  = tid >> 1;          // 0..127
            const int col0 = (tid & 1) * 8;     // 0 or 8
            const float* wp = W + (size_t)(o0 + row) * C + c0 + col0;
            #pragma unroll
            for (int j = 0; j < 8; j++) As[col0 + j][row] = wp[j];
        }
        // Load x chunk: 16 rows(c) x 128 cols(p); fully coalesced.
        {
            #pragma unroll
            for (int i = 0; i < 8; i++) {
                const int idx = tid + i * 256;
                const int k = idx >> 7, p = idx & 127;
                Bs[k][p] = xb[(size_t)(c0 + k) * P + p0 + p];
            }
        }
        __syncthreads();

        #pragma unroll
        for (int k = 0; k < 16; k++) {
            float a[8], bb[8];
            #pragma unroll
            for (int i = 0; i < 8; i++) a[i]  = As[k][ty * 8 + i];
            #pragma unroll
            for (int j = 0; j < 8; j++) bb[j] = Bs[k][tx * 8 + j];
            #pragma unroll
            for (int i = 0; i < 8; i++)
                #pragma unroll
                for (int j = 0; j < 8; j++) acc[i][j] += a[i] * bb[j];
        }
        __syncthreads();
    }

    float* outb = g_logits + (size_t)b * ELEMS;
    #pragma unroll
    for (int i = 0; i < 8; i++) {
        const int o = o0 + ty * 8 + i;
        const float bv = bias[o];
        #pragma unroll
        for (int j = 0; j < 8; j++)
            outb[(size_t)o * P + p0 + tx * 8 + j] = acc[i][j] + bv;
    }
}

// ---------------------------------------------------------------------------
// K2: per-sample softmax stats (max + 1/sum(exp)) over 131072 logits.
// ---------------------------------------------------------------------------
__global__ __launch_bounds__(256) void softmax_stats_kernel()
{
    const int b = blockIdx.x;
    const float* lg = g_logits + (size_t)b * ELEMS;
    __shared__ float red[256];
    const int tid = threadIdx.x;

    float mx = -1e30f;
    for (int i = tid; i < ELEMS; i += 256) mx = fmaxf(mx, lg[i]);
    red[tid] = mx; __syncthreads();
    for (int s = 128; s > 0; s >>= 1) {
        if (tid < s) red[tid] = fmaxf(red[tid], red[tid + s]);
        __syncthreads();
    }
    mx = red[0]; __syncthreads();

    float sum = 0.f;
    for (int i = tid; i < ELEMS; i += 256) sum += expf(lg[i] - mx);
    red[tid] = sum; __syncthreads();
    for (int s = 128; s > 0; s >>= 1) {
        if (tid < s) red[tid] += red[tid + s];
        __syncthreads();
    }
    if (tid == 0) { g_max[b] = mx; g_invsum[b] = 1.0f / red[0]; }
}

// ---------------------------------------------------------------------------
// K3: prototypes. grid (32 channel-groups, 5 ways), 256 threads (8 warps).
// Each warp handles 2 channels; lanes stride over pixels (coalesced).
// ---------------------------------------------------------------------------
__global__ __launch_bounds__(256) void proto_kernel(const float* __restrict__ x)
{
    const int way  = blockIdx.y;
    const int cg   = blockIdx.x;              // 0..31 -> 16 channels each
    const int w    = threadIdx.x >> 5;        // warp 0..7
    const int lane = threadIdx.x & 31;

    float mxv[SHOT], isv[SHOT];
    #pragma unroll
    for (int s = 0; s < SHOT; s++) {
        const int b = way * 20 + s;
        mxv[s] = g_max[b]; isv[s] = g_invsum[b];
    }

    #pragma unroll
    for (int j = 0; j < 2; j++) {
        const int c = cg * 16 + w * 2 + j;
        float acc = 0.f;
        #pragma unroll
        for (int s = 0; s < SHOT; s++) {
            const int b = way * 20 + s;
            const float* xp = x        + (size_t)b * ELEMS + (size_t)c * P;
            const float* lp = g_logits + (size_t)b * ELEMS + (size_t)c * P;
            #pragma unroll
            for (int i = 0; i < 8; i++) {
                const int p = lane + i * 32;
                acc += xp[p] * expf(lp[p] - mxv[s]) * isv[s];
            }
        }
        #pragma unroll
        for (int o = 16; o > 0; o >>= 1)
            acc += __shfl_xor_sync(0xffffffffu, acc, o);
        if (lane == 0) g_proto[way * C + c] = acc * (1.0f / 1280.0f);
    }
}

// ---------------------------------------------------------------------------
// K4: scoring. One block per query (75). Thread = one pixel f (256 threads).
// Loop over 512 channels: q = x*mask, accumulate |q|^2 and 5 dot products
// against smem-resident prototypes. Then 5-way softmax and spatial mean.
// ---------------------------------------------------------------------------
__global__ __launch_bounds__(256) void score_kernel(
    const float* __restrict__ x, float* __restrict__ out)
{
    const int n   = blockIdx.x;          // 0..74
    const int way = n / 15;
    const int qi  = n % 15;
    const int b   = way * 20 + SHOT + qi;

    __shared__ float s_sm[WAY * C];
    __shared__ float sn_sm[WAY];
    __shared__ float acc_out[WAY];

    const int tid = threadIdx.x;
    for (int i = tid; i < WAY * C; i += 256) s_sm[i] = g_proto[i];
    if (tid < WAY) acc_out[tid] = 0.f;
    __syncthreads();

    if (tid < 32) {
        #pragma unroll
        for (int m = 0; m < WAY; m++) {
            float v = 0.f;
            for (int c = tid; c < C; c += 32) { float t = s_sm[m * C + c]; v += t * t; }
            #pragma unroll
            for (int o = 16; o > 0; o >>= 1) v += __shfl_xor_sync(0xffffffffu, v, o);
            if (tid == 0) sn_sm[m] = fmaxf(sqrtf(v), 1e-8f);
        }
    }
    __syncthreads();

    const float mx = g_max[b];
    const float is = g_invsum[b];
    const float* xp = x        + (size_t)b * ELEMS;
    const float* lp = g_logits + (size_t)b * ELEMS;
    const int f = tid;

    float qq = 0.f, d0 = 0.f, d1 = 0.f, d2 = 0.f, d3 = 0.f, d4 = 0.f;
    for (int c = 0; c < C; c++) {
        const float xv = xp[(size_t)c * P + f];
        const float q  = xv * expf(lp[(size_t)c * P + f] - mx) * is;
        qq += q * q;
        d0 += q * s_sm[c];
        d1 += q * s_sm[C + c];
        d2 += q * s_sm[2 * C + c];
        d3 += q * s_sm[3 * C + c];
        d4 += q * s_sm[4 * C + c];
    }
    const float qn = fmaxf(sqrtf(qq), 1e-8f);

    float sc[WAY] = {d0, d1, d2, d3, d4};
    float m5 = -1e30f;
    #pragma unroll
    for (int m = 0; m < WAY; m++) {
        sc[m] = 10.0f * sc[m] / (qn * sn_sm[m]);
        m5 = fmaxf(m5, sc[m]);
    }
    float se = 0.f;
    #pragma unroll
    for (int m = 0; m < WAY; m++) { sc[m] = expf(sc[m] - m5); se += sc[m]; }
    const float inv = 1.0f / (se * 256.0f);
    #pragma unroll
    for (int m = 0; m < WAY; m++) atomicAdd(&acc_out[m], sc[m] * inv);
    __syncthreads();
    if (tid < WAY) out[n * WAY + tid] = acc_out[tid];
}

// ---------------------------------------------------------------------------
extern "C" void kernel_launch(void* const* d_in, const int* in_sizes, int n_in,
                              void* d_out, int out_size)
{
    const float* x    = (const float*)d_in[0];
    const float* W    = (const float*)d_in[1];
    const float* bias = (const float*)d_in[2];
    float* out = (float*)d_out;

    gemm_kernel<<<dim3(2, 4, NSAMP), 256>>>(x, W, bias);   // 2 p-tiles, 4 o-tiles, 100 samples
    softmax_stats_kernel<<<NSAMP, 256>>>();
    proto_kernel<<<dim3(32, WAY), 256>>>(x);
    score_kernel<<<NQ, 256>>>(x, out);
}

// round 2
// speedup vs baseline: 3.5091x; 3.5091x over previous
#include <cuda_runtime.h>
#include <cuda_bf16.h>
#include <math.h>
#include <stdint.h>

// x: (100, 512, 16, 16) fp32 ; W: (512,512) (outC,inC) ; b: (512,) ; out: (75,5)
#define NSAMP 100
#define C 512
#define P 256
#define ELEMS (C*P)
#define WAY 5
#define SHOT 5
#define NQ 75
#define NCHUNK 8          // channel chunks for score partial
#define CPERCHUNK (C/NCHUNK)

__device__ float g_logits[NSAMP * ELEMS];        // 52 MB
__device__ float g_sum[NSAMP];                   // sum of exp(logit) per sample
__device__ float g_proto[WAY * C];
__device__ float g_part[NQ * NCHUNK * P * 8];    // per (n,chunk,f): qq,d0..d4,pad

// ---------------------------------------------------------------------------
__global__ void zero_kernel()
{
    const int i = threadIdx.x;
    if (i < NSAMP) g_sum[i] = 0.f;
}

// ---------------------------------------------------------------------------
// tf32 helpers
// ---------------------------------------------------------------------------
__device__ __forceinline__ uint32_t f2tf(float f)
{
    uint32_t r;
    asm("cvt.rna.tf32.f32 %0, %1;" : "=r"(r) : "f"(f));
    return r;
}

__device__ __forceinline__ void mma_tf32(float (&d)[4], const uint32_t (&a)[4],
                                         const uint32_t (&b)[2])
{
    asm volatile(
        "mma.sync.aligned.m16n8k8.row.col.f32.tf32.tf32.f32 "
        "{%0,%1,%2,%3}, {%4,%5,%6,%7}, {%8,%9}, {%0,%1,%2,%3};\n"
        : "+f"(d[0]), "+f"(d[1]), "+f"(d[2]), "+f"(d[3])
        : "r"(a[0]), "r"(a[1]), "r"(a[2]), "r"(a[3]), "r"(b[0]), "r"(b[1]));
}

// ---------------------------------------------------------------------------
// K1: logits[b][o][p] = sum_c W[o][c] * x[b][c][p] (+bias), tf32 tensor cores.
// Block tile 128(o) x 128(p), K-chunk 32. 256 threads = 8 warps (2x4),
// warp tile 64(o) x 32(p) -> 4x4 m16n8k8 fragments.
// Epilogue: write logits + accumulate sum(exp(logit)) into g_sum[b].
// ---------------------------------------------------------------------------
#define AS_STRIDE 36
#define BS_STRIDE 136

__global__ __launch_bounds__(256) void gemm_tf32_kernel(
    const float* __restrict__ x, const float* __restrict__ W,
    const float* __restrict__ bias)
{
    const int b  = blockIdx.z;
    const int o0 = blockIdx.y * 128;
    const int p0 = blockIdx.x * 128;

    __shared__ uint32_t as_u[128 * AS_STRIDE];   // [o_local][k_local]
    __shared__ uint32_t bs_u[32 * BS_STRIDE];    // [k_local][p_local]
    __shared__ float red[256];

    const int tid  = threadIdx.x;
    const int warp = tid >> 5;
    const int lane = tid & 31;
    const int wm   = (warp >> 2) * 64;
    const int wn   = (warp & 3) * 32;
    const int grp  = lane >> 2;
    const int tig  = lane & 3;

    const float* xb = x + (size_t)b * ELEMS;

    float acc[4][4][4];
    #pragma unroll
    for (int mi = 0; mi < 4; mi++)
        #pragma unroll
        for (int ni = 0; ni < 4; ni++)
            #pragma unroll
            for (int r = 0; r < 4; r++) acc[mi][ni][r] = 0.f;

    for (int c0 = 0; c0 < C; c0 += 32) {
        // W tile: 128 rows(o) x 32 cols(c)
        #pragma unroll
        for (int i = 0; i < 4; i++) {
            const int idx = tid + i * 256;
            const int row = idx >> 3;
            const int q   = (idx & 7) * 4;
            const float4 v = *(const float4*)(W + (size_t)(o0 + row) * C + c0 + q);
            uint4 u;
            u.x = f2tf(v.x); u.y = f2tf(v.y); u.z = f2tf(v.z); u.w = f2tf(v.w);
            *(uint4*)(as_u + row * AS_STRIDE + q) = u;
        }
        // x tile: 32 rows(c) x 128 cols(p)
        #pragma unroll
        for (int i = 0; i < 4; i++) {
            const int idx = tid + i * 256;
            const int k   = idx >> 5;
            const int q   = (idx & 31) * 4;
            const float4 v = *(const float4*)(xb + (size_t)(c0 + k) * P + p0 + q);
            uint4 u;
            u.x = f2tf(v.x); u.y = f2tf(v.y); u.z = f2tf(v.z); u.w = f2tf(v.w);
            *(uint4*)(bs_u + k * BS_STRIDE + q) = u;
        }
        __syncthreads();

        #pragma unroll
        for (int kk = 0; kk < 32; kk += 8) {
            uint32_t af[4][4], bf[4][2];
            #pragma unroll
            for (int mi = 0; mi < 4; mi++) {
                const int base = wm + mi * 16;
                af[mi][0] = as_u[(base + grp)     * AS_STRIDE + kk + tig];
                af[mi][1] = as_u[(base + grp + 8) * AS_STRIDE + kk + tig];
                af[mi][2] = as_u[(base + grp)     * AS_STRIDE + kk + tig + 4];
                af[mi][3] = as_u[(base + grp + 8) * AS_STRIDE + kk + tig + 4];
            }
            #pragma unroll
            for (int ni = 0; ni < 4; ni++) {
                const int col = wn + ni * 8 + grp;
                bf[ni][0] = bs_u[(kk + tig)     * BS_STRIDE + col];
                bf[ni][1] = bs_u[(kk + tig + 4) * BS_STRIDE + col];
            }
            #pragma unroll
            for (int mi = 0; mi < 4; mi++)
                #pragma unroll
                for (int ni = 0; ni < 4; ni++)
                    mma_tf32(acc[mi][ni], af[mi], bf[ni]);
        }
        __syncthreads();
    }

    // Epilogue: bias, store logits, local sum of exp
    float* outb = g_logits + (size_t)b * ELEMS;
    float esum = 0.f;
    #pragma unroll
    for (int mi = 0; mi < 4; mi++) {
        const int o_r0 = o0 + wm + mi * 16 + grp;
        const int o_r1 = o_r0 + 8;
        const float bv0 = bias[o_r0];
        const float bv1 = bias[o_r1];
        #pragma unroll
        for (int ni = 0; ni < 4; ni++) {
            const int p_c = p0 + wn + ni * 8 + 2 * tig;
            const float v0 = acc[mi][ni][0] + bv0;
            const float v1 = acc[mi][ni][1] + bv0;
            const float v2 = acc[mi][ni][2] + bv1;
            const float v3 = acc[mi][ni][3] + bv1;
            *(float2*)(outb + (size_t)o_r0 * P + p_c) = make_float2(v0, v1);
            *(float2*)(outb + (size_t)o_r1 * P + p_c) = make_float2(v2, v3);
            esum += expf(v0) + expf(v1) + expf(v2) + expf(v3);
        }
    }
    red[tid] = esum;
    __syncthreads();
    for (int s = 128; s > 0; s >>= 1) {
        if (tid < s) red[tid] += red[tid + s];
        __syncthreads();
    }
    if (tid == 0) atomicAdd(&g_sum[b], red[0]);
}

// ---------------------------------------------------------------------------
// K2: prototypes. grid (32 channel-groups, 5 ways), 8 warps; warp = 2 channels.
// mask = exp(logit)/sum  (no max subtraction needed; logits bounded)
// ---------------------------------------------------------------------------
__global__ __launch_bounds__(256) void proto_kernel(const float* __restrict__ x)
{
    const int way  = blockIdx.y;
    const int cg   = blockIdx.x;
    const int w    = threadIdx.x >> 5;
    const int lane = threadIdx.x & 31;

    float isv[SHOT];
    #pragma unroll
    for (int s = 0; s < SHOT; s++) isv[s] = 1.0f / g_sum[way * 20 + s];

    #pragma unroll
    for (int j = 0; j < 2; j++) {
        const int c = cg * 16 + w * 2 + j;
        float acc = 0.f;
        #pragma unroll
        for (int s = 0; s < SHOT; s++) {
            const int b = way * 20 + s;
            const float* xp = x        + (size_t)b * ELEMS + (size_t)c * P;
            const float* lp = g_logits + (size_t)b * ELEMS + (size_t)c * P;
            #pragma unroll
            for (int i = 0; i < 8; i++) {
                const int p = lane + i * 32;
                acc += xp[p] * expf(lp[p]) * isv[s];
            }
        }
        #pragma unroll
        for (int o = 16; o > 0; o >>= 1)
            acc += __shfl_xor_sync(0xffffffffu, acc, o);
        if (lane == 0) g_proto[way * C + c] = acc * (1.0f / 1280.0f);
    }
}

// ---------------------------------------------------------------------------
// K3: score partial. grid (8 chunks, 75 queries), thread = pixel f.
// Each block handles 64 channels; writes partial (qq, d0..d4) per pixel.
// ---------------------------------------------------------------------------
__global__ __launch_bounds__(256) void score_partial_kernel(const float* __restrict__ x)
{
    const int chunk = blockIdx.x;
    const int n     = blockIdx.y;
    const int way   = n / 15;
    const int b     = way * 20 + SHOT + (n % 15);
    const int tid   = threadIdx.x;

    __shared__ float s_sm[WAY][CPERCHUNK];
    for (int i = tid; i < WAY * CPERCHUNK; i += 256)
        s_sm[i >> 6][i & 63] = g_proto[(i >> 6) * C + chunk * CPERCHUNK + (i & 63)];
    __syncthreads();

    const float inv = 1.0f / g_sum[b];
    const float* xp = x        + (size_t)b * ELEMS + (size_t)chunk * CPERCHUNK * P;
    const float* lp = g_logits + (size_t)b * ELEMS + (size_t)chunk * CPERCHUNK * P;
    const int f = tid;

    float qq = 0.f, d0 = 0.f, d1 = 0.f, d2 = 0.f, d3 = 0.f, d4 = 0.f;
    #pragma unroll 4
    for (int c = 0; c < CPERCHUNK; c++) {
        const float q = xp[(size_t)c * P + f] * expf(lp[(size_t)c * P + f]) * inv;
        qq += q * q;
        d0 += q * s_sm[0][c];
        d1 += q * s_sm[1][c];
        d2 += q * s_sm[2][c];
        d3 += q * s_sm[3][c];
        d4 += q * s_sm[4][c];
    }
    float* pp = g_part + (((size_t)n * NCHUNK + chunk) * P + f) * 8;
    *(float4*)(pp)     = make_float4(qq, d0, d1, d2);
    *(float4*)(pp + 4) = make_float4(d3, d4, 0.f, 0.f);
}

// ---------------------------------------------------------------------------
// K4: final. 75 blocks, thread = pixel. Reduce 8 chunks, cosine + softmax + mean.
// ---------------------------------------------------------------------------
__global__ __launch_bounds__(256) void final_kernel(float* __restrict__ out)
{
    const int n   = blockIdx.x;
    const int tid = threadIdx.x;

    __shared__ float sn_sm[WAY];
    __shared__ float accum[WAY];
    if (tid < WAY) accum[tid] = 0.f;

    if (tid < WAY * 32) {
        const int m = tid >> 5, lane = tid & 31;
        float v = 0.f;
        #pragma unroll
        for (int i = 0; i < C / 32; i++) {
            const float t = g_proto[m * C + lane + i * 32];
            v += t * t;
        }
        #pragma unroll
        for (int o = 16; o > 0; o >>= 1) v += __shfl_xor_sync(0xffffffffu, v, o);
        if (lane == 0) sn_sm[m] = fmaxf(sqrtf(v), 1e-8f);
    }
    __syncthreads();

    const int f = tid;
    float qq = 0.f, d[WAY] = {0.f, 0.f, 0.f, 0.f, 0.f};
    #pragma unroll
    for (int ch = 0; ch < NCHUNK; ch++) {
        const float* pp = g_part + (((size_t)n * NCHUNK + ch) * P + f) * 8;
        const float4 v0 = *(const float4*)(pp);
        const float4 v1 = *(const float4*)(pp + 4);
        qq += v0.x; d[0] += v0.y; d[1] += v0.z; d[2] += v0.w;
        d[3] += v1.x; d[4] += v1.y;
    }
    const float qn = fmaxf(sqrtf(qq), 1e-8f);

    float sc[WAY], m5 = -1e30f;
    #pragma unroll
    for (int m = 0; m < WAY; m++) {
        sc[m] = 10.0f * d[m] / (qn * sn_sm[m]);
        m5 = fmaxf(m5, sc[m]);
    }
    float se = 0.f;
    #pragma unroll
    for (int m = 0; m < WAY; m++) { sc[m] = expf(sc[m] - m5); se += sc[m]; }
    const float inv = 1.0f / (se * (float)P);
    #pragma unroll
    for (int m = 0; m < WAY; m++) atomicAdd(&accum[m], sc[m] * inv);
    __syncthreads();
    if (tid < WAY) out[n * WAY + tid] = accum[tid];
}

// ---------------------------------------------------------------------------
extern "C" void kernel_launch(void* const* d_in, const int* in_sizes, int n_in,
                              void* d_out, int out_size)
{
    const float* x    = (const float*)d_in[0];
    const float* W    = (const float*)d_in[1];
    const float* bias = (const float*)d_in[2];
    float* out = (float*)d_out;

    zero_kernel<<<1, 128>>>();
    gemm_tf32_kernel<<<dim3(2, 4, NSAMP), 256>>>(x, W, bias);
    proto_kernel<<<dim3(32, WAY), 256>>>(x);
    score_partial_kernel<<<dim3(NCHUNK, NQ), 256>>>(x);
    final_kernel<<<NQ, 256>>>(out);
}

// round 5
// speedup vs baseline: 3.9922x; 1.1377x over previous
#include <cuda_runtime.h>
#include <cuda_fp16.h>
#include <math.h>
#include <stdint.h>

// x: (100, 512, 16, 16) fp32 ; W: (512,512) (outC,inC) ; b: (512,) ; out: (75,5)
#define NSAMP 100
#define C 512
#define P 256
#define ELEMS (C*P)
#define WAY 5
#define SHOT 5
#define NQ 75
#define NCHUNK 4
#define CPERCHUNK 128

__device__ __half g_logits[NSAMP * ELEMS];     // [b][f][c] fp16, 26 MB
__device__ float  g_sum[NSAMP];                // sum of exp(logit) per sample
__device__ float  g_protoAcc[WAY * C];         // unnormalized prototypes
__device__ float  g_part[NQ * NCHUNK * P * 8];

// ===========================================================================
__device__ __forceinline__ uint32_t smem_u32(const void* p) {
    uint32_t a;
    asm("{ .reg .u64 t; cvta.to.shared.u64 t, %1; cvt.u32.u64 %0, t; }"
        : "=r"(a) : "l"(p));
    return a;
}
__device__ __forceinline__ void ldsm4(uint32_t (&r)[4], uint32_t addr) {
    asm volatile("ldmatrix.sync.aligned.m8n8.x4.shared.b16 {%0,%1,%2,%3}, [%4];"
                 : "=r"(r[0]), "=r"(r[1]), "=r"(r[2]), "=r"(r[3]) : "r"(addr));
}
__device__ __forceinline__ void mma16816(float (&d)[4], const uint32_t (&a)[4],
                                         uint32_t b0, uint32_t b1) {
    asm volatile(
        "mma.sync.aligned.m16n8k16.row.col.f32.f16.f16.f32 "
        "{%0,%1,%2,%3},{%4,%5,%6,%7},{%8,%9},{%0,%1,%2,%3};"
        : "+f"(d[0]), "+f"(d[1]), "+f"(d[2]), "+f"(d[3])
        : "r"(a[0]), "r"(a[1]), "r"(a[2]), "r"(a[3]), "r"(b0), "r"(b1));
}
__device__ __forceinline__ uint32_t pkh(float a, float b) {
    __half2 h = __floats2half2_rn(a, b);
    return *(uint32_t*)&h;
}
// 16B-chunk XOR swizzle inside a 64B row (4 chunks): conflict-free for both
// STS.128 (8 consecutive rows per phase) and ldmatrix row reads.
__device__ __forceinline__ int swz(int row, int ch) {
    return row * 64 + ((ch ^ ((row >> 1) & 3)) << 4);
}

// ===========================================================================
// K0: zero accumulators
// ===========================================================================
__global__ void zero_kernel()
{
    for (int i = threadIdx.x; i < NSAMP + WAY * C; i += 256) {
        if (i < NSAMP) g_sum[i] = 0.f;
        else g_protoAcc[i - NSAMP] = 0.f;
    }
}

// ===========================================================================
// K1: fp16 mma.sync GEMM.  D[p(128), o(128)] = sum_c x[c][p] * W[o][c].
// A = x^T (transpose-on-store during LDG->STS), B = W (natural k-contiguous).
// BK=32, double-buffered smem, register prefetch. 8 warps, warp tile 64x32.
// Epilogue: +bias, sum(exp) -> g_sum, fp16 logits [b][f][c] via smem staging.
// ===========================================================================
#define STAGE_PITCH 136   // halves, staging pitch

__global__ __launch_bounds__(256) void gemm_mma(
    const float* __restrict__ x, const float* __restrict__ W,
    const float* __restrict__ bias)
{
    // A stages @0,@8192 ; B stages @16384,@24576 ; reused as 128x136 half staging
    __shared__ __align__(128) uint8_t sm[34816];
    __shared__ float sm_red[8];
    __shared__ float sm_bias[128];

    const int b   = blockIdx.z;
    const int p0  = blockIdx.x * 128;
    const int o0  = blockIdx.y * 128;
    const int tid = threadIdx.x;
    const int wid = tid >> 5;
    const int lane = tid & 31;
    const int wm = (wid & 1) * 64;       // warp row (p) base
    const int wn = (wid >> 1) * 32;      // warp col (o) base

    if (tid < 128) sm_bias[tid] = bias[o0 + tid];

    const uint32_t smb = smem_u32(sm);

    // ---- loader mappings ----
    // A: thread -> pixel pa (coalesced across lanes), chunk pair cpa (c-range 16)
    const int pa  = tid & 127;
    const int cpa = tid >> 7;                       // 0/1
    const float* xb = x + (size_t)b * ELEMS + p0 + pa;
    const int aOff0 = swz(pa, cpa * 2 + 0);
    const int aOff1 = swz(pa, cpa * 2 + 1);
    // B: chunks cid = tid and tid+256 ; cid -> (o = cid>>2, ch = cid&3)
    const int ob0 = tid >> 2, chb = tid & 3;
    const int ob1 = ob0 + 64;
    const float* wrow0 = W + (size_t)(o0 + ob0) * C + chb * 8;
    const float* wrow1 = W + (size_t)(o0 + ob1) * C + chb * 8;
    const int bOff0 = 16384 + swz(ob0, chb);
    const int bOff1 = 16384 + swz(ob1, chb);

    // ---- ldmatrix addresses (per kstep, stage-relative) ----
    uint32_t aLd[2][4], bLd[2][2];
    #pragma unroll
    for (int ks = 0; ks < 2; ks++) {
        #pragma unroll
        for (int mi = 0; mi < 4; mi++) {
            const int row = wm + mi * 16 + (lane & 15);
            aLd[ks][mi] = smb + swz(row, ks * 2 + (lane >> 4));
        }
        #pragma unroll
        for (int np = 0; np < 2; np++) {
            const int g = lane >> 3;
            const int row = wn + np * 16 + ((g >> 1) << 3) + (lane & 7);
            bLd[ks][np] = smb + 16384 + swz(row, ks * 2 + (g & 1));
        }
    }

    float acc[4][4][4];
    #pragma unroll
    for (int mi = 0; mi < 4; mi++)
        #pragma unroll
        for (int ni = 0; ni < 4; ni++)
            #pragma unroll
            for (int r = 0; r < 4; r++) acc[mi][ni][r] = 0.f;

    float fa[16];
    float4 fb[4];

    // prefetch + store tile 0
    {
        const float* ap = xb + (size_t)(cpa * 16) * P;
        #pragma unroll
        for (int j = 0; j < 16; j++) fa[j] = ap[j * P];
        fb[0] = *(const float4*)(wrow0);
        fb[1] = *(const float4*)(wrow0 + 4);
        fb[2] = *(const float4*)(wrow1);
        fb[3] = *(const float4*)(wrow1 + 4);
        #pragma unroll
        for (int h = 0; h < 2; h++) {
            uint4 u;
            u.x = pkh(fa[h*8+0], fa[h*8+1]); u.y = pkh(fa[h*8+2], fa[h*8+3]);
            u.z = pkh(fa[h*8+4], fa[h*8+5]); u.w = pkh(fa[h*8+6], fa[h*8+7]);
            *(uint4*)(sm + (h ? aOff1 : aOff0)) = u;
        }
        uint4 u0, u1;
        u0.x = pkh(fb[0].x, fb[0].y); u0.y = pkh(fb[0].z, fb[0].w);
        u0.z = pkh(fb[1].x, fb[1].y); u0.w = pkh(fb[1].z, fb[1].w);
        u1.x = pkh(fb[2].x, fb[2].y); u1.y = pkh(fb[2].z, fb[2].w);
        u1.z = pkh(fb[3].x, fb[3].y); u1.w = pkh(fb[3].z, fb[3].w);
        *(uint4*)(sm + bOff0) = u0;
        *(uint4*)(sm + bOff1) = u1;
    }
    __syncthreads();

    for (int kt = 0; kt < 16; kt++) {
        // prefetch next tile into registers (overlaps with MMAs below)
        if (kt < 15) {
            const int c0 = (kt + 1) * 32;
            const float* ap = xb + (size_t)(c0 + cpa * 16) * P;
            #pragma unroll
            for (int j = 0; j < 16; j++) fa[j] = ap[j * P];
            fb[0] = *(const float4*)(wrow0 + c0);
            fb[1] = *(const float4*)(wrow0 + c0 + 4);
            fb[2] = *(const float4*)(wrow1 + c0);
            fb[3] = *(const float4*)(wrow1 + c0 + 4);
        }

        const uint32_t stA = (kt & 1) * 8192;
        #pragma unroll
        for (int ks = 0; ks < 2; ks++) {
            uint32_t ar[4][4], br[2][4];
            #pragma unroll
            for (int mi = 0; mi < 4; mi++) ldsm4(ar[mi], aLd[ks][mi] + stA);
            #pragma unroll
            for (int np = 0; np < 2; np++) ldsm4(br[np], bLd[ks][np] + stA);
            #pragma unroll
            for (int mi = 0; mi < 4; mi++)
                #pragma unroll
                for (int ni = 0; ni < 4; ni++)
                    mma16816(acc[mi][ni], ar[mi],
                             br[ni >> 1][(ni & 1) * 2], br[ni >> 1][(ni & 1) * 2 + 1]);
        }

        if (kt < 15) {
            const uint32_t st = ((kt + 1) & 1) * 8192;
            #pragma unroll
            for (int h = 0; h < 2; h++) {
                uint4 u;
                u.x = pkh(fa[h*8+0], fa[h*8+1]); u.y = pkh(fa[h*8+2], fa[h*8+3]);
                u.z = pkh(fa[h*8+4], fa[h*8+5]); u.w = pkh(fa[h*8+6], fa[h*8+7]);
                *(uint4*)(sm + st + (h ? aOff1 : aOff0)) = u;
            }
            uint4 u0, u1;
            u0.x = pkh(fb[0].x, fb[0].y); u0.y = pkh(fb[0].z, fb[0].w);
            u0.z = pkh(fb[1].x, fb[1].y); u0.w = pkh(fb[1].z, fb[1].w);
            u1.x = pkh(fb[2].x, fb[2].y); u1.y = pkh(fb[2].z, fb[2].w);
            u1.z = pkh(fb[3].x, fb[3].y); u1.w = pkh(fb[3].z, fb[3].w);
            *(uint4*)(sm + st + bOff0) = u0;
            *(uint4*)(sm + st + bOff1) = u1;
            __syncthreads();
        }
    }
    __syncthreads();   // all MMA reads done -> smem reusable as staging

    // ---- epilogue: bias + exp-sum + fp16 staging ----
    __half* stg = (__half*)sm;
    float esum = 0.f;
    #pragma unroll
    for (int mi = 0; mi < 4; mi++) {
        const int r0 = wm + mi * 16 + (lane >> 2);
        #pragma unroll
        for (int ni = 0; ni < 4; ni++) {
            const int cc = wn + ni * 8 + 2 * (lane & 3);
            const float bv0 = sm_bias[cc], bv1 = sm_bias[cc + 1];
            const float v0 = acc[mi][ni][0] + bv0;
            const float v1 = acc[mi][ni][1] + bv1;
            const float v2 = acc[mi][ni][2] + bv0;
            const float v3 = acc[mi][ni][3] + bv1;
            esum += __expf(v0) + __expf(v1) + __expf(v2) + __expf(v3);
            *(__half2*)(stg + (size_t)r0 * STAGE_PITCH + cc) = __floats2half2_rn(v0, v1);
            *(__half2*)(stg + (size_t)(r0 + 8) * STAGE_PITCH + cc) = __floats2half2_rn(v2, v3);
        }
    }
    #pragma unroll
    for (int o = 16; o > 0; o >>= 1) esum += __shfl_xor_sync(0xffffffffu, esum, o);
    if (lane == 0) sm_red[wid] = esum;
    __syncthreads();
    if (tid == 0) {
        float s = 0.f;
        #pragma unroll
        for (int i = 0; i < 8; i++) s += sm_red[i];
        atomicAdd(&g_sum[b], s);
    }

    // coalesced fp16 store: g_logits[b][f=p0+row][c=o0+seg*8 .. +7]
    __half* dst = g_logits + (size_t)b * ELEMS;
    #pragma unroll
    for (int k = 0; k < 8; k++) {
        const int idx = tid + k * 256;
        const int row = idx >> 4;
        const int seg = idx & 15;
        *(uint4*)(dst + (size_t)(p0 + row) * C + o0 + seg * 8) =
            *(const uint4*)(stg + (size_t)row * STAGE_PITCH + seg * 8);
    }
}

// ===========================================================================
// K2: prototypes (support samples). grid (4 c-groups, 25 (way,shot)).
// thread = pixel f; x reads coalesced across lanes, logits vectorized.
// ===========================================================================
__global__ __launch_bounds__(256) void proto_kernel(const float* __restrict__ x)
{
    const int way = blockIdx.y / SHOT;
    const int sh  = blockIdx.y % SHOT;
    const int b   = way * 20 + sh;
    const int c0  = blockIdx.x * 128;
    const int f    = threadIdx.x;
    const int lane = f & 31;

    __shared__ float acc[128];
    for (int i = threadIdx.x; i < 128; i += 256) acc[i] = 0.f;
    __syncthreads();

    const float inv = 1.0f / g_sum[b];
    const __half* lg = g_logits + (size_t)b * ELEMS + (size_t)f * C + c0;
    const float*  xb = x        + (size_t)b * ELEMS + (size_t)c0 * P + f;

    for (int c8 = 0; c8 < 16; c8++) {
        const uint4 u = *(const uint4*)(lg + c8 * 8);
        #pragma unroll
        for (int t = 0; t < 4; t++) {
            const float2 lf = __half22float2(((const __half2*)&u)[t]);
            const int c = c8 * 8 + t * 2;
            float v0 = xb[(size_t)c * P]       * __expf(lf.x) * inv;
            float v1 = xb[(size_t)(c + 1) * P] * __expf(lf.y) * inv;
            #pragma unroll
            for (int o = 16; o > 0; o >>= 1) {
                v0 += __shfl_xor_sync(0xffffffffu, v0, o);
                v1 += __shfl_xor_sync(0xffffffffu, v1, o);
            }
            if (lane == 0) { atomicAdd(&acc[c], v0); atomicAdd(&acc[c + 1], v1); }
        }
    }
    __syncthreads();
    if (threadIdx.x < 128)
        atomicAdd(&g_protoAcc[way * C + c0 + threadIdx.x], acc[threadIdx.x]);
}

// ===========================================================================
// K3: score partials. grid (4 chunks, 75 queries); thread = pixel f.
// ===========================================================================
__global__ __launch_bounds__(256) void score_partial_kernel(const float* __restrict__ x)
{
    const int chunk = blockIdx.x;
    const int n     = blockIdx.y;
    const int way   = n / 15;
    const int b     = way * 20 + SHOT + (n % 15);
    const int tid   = threadIdx.x;
    const int c0    = chunk * CPERCHUNK;

    __shared__ float s_sm[WAY][CPERCHUNK];
    for (int i = tid; i < WAY * CPERCHUNK; i += 256)
        s_sm[i / CPERCHUNK][i % CPERCHUNK] =
            g_protoAcc[(i / CPERCHUNK) * C + c0 + (i % CPERCHUNK)];
    __syncthreads();

    const float inv = 1.0f / g_sum[b];
    const __half* lg = g_logits + (size_t)b * ELEMS + (size_t)tid * C + c0;
    const float*  xb = x        + (size_t)b * ELEMS + (size_t)c0 * P + tid;

    float qq = 0.f, d0 = 0.f, d1 = 0.f, d2 = 0.f, d3 = 0.f, d4 = 0.f;
    for (int c8 = 0; c8 < CPERCHUNK / 8; c8++) {
        const uint4 u = *(const uint4*)(lg + c8 * 8);
        #pragma unroll
        for (int t = 0; t < 4; t++) {
            const float2 lf = __half22float2(((const __half2*)&u)[t]);
            const int c = c8 * 8 + t * 2;
            const float q0 = xb[(size_t)c * P]       * __expf(lf.x) * inv;
            const float q1 = xb[(size_t)(c + 1) * P] * __expf(lf.y) * inv;
            qq += q0 * q0 + q1 * q1;
            d0 += q0 * s_sm[0][c] + q1 * s_sm[0][c + 1];
            d1 += q0 * s_sm[1][c] + q1 * s_sm[1][c + 1];
            d2 += q0 * s_sm[2][c] + q1 * s_sm[2][c + 1];
            d3 += q0 * s_sm[3][c] + q1 * s_sm[3][c + 1];
            d4 += q0 * s_sm[4][c] + q1 * s_sm[4][c + 1];
        }
    }
    float* pp = g_part + (((size_t)n * NCHUNK + chunk) * P + tid) * 8;
    *(float4*)(pp)     = make_float4(qq, d0, d1, d2);
    *(float4*)(pp + 4) = make_float4(d3, d4, 0.f, 0.f);
}

// ===========================================================================
// K4: final. 75 blocks; thread = pixel. Cosine, 5-way softmax, spatial mean.
// (prototype scale cancels in cosine similarity -> raw protoAcc is fine)
// ===========================================================================
__global__ __launch_bounds__(256) void final_kernel(float* __restrict__ out)
{
    const int n   = blockIdx.x;
    const int tid = threadIdx.x;

    __shared__ float sn_sm[WAY];
    __shared__ float accum[WAY];
    if (tid < WAY) accum[tid] = 0.f;

    if (tid < WAY * 32) {
        const int m = tid >> 5, lane = tid & 31;
        float v = 0.f;
        #pragma unroll
        for (int i = 0; i < C / 32; i++) {
            const float t = g_protoAcc[m * C + lane + i * 32];
            v += t * t;
        }
        #pragma unroll
        for (int o = 16; o > 0; o >>= 1) v += __shfl_xor_sync(0xffffffffu, v, o);
        if (lane == 0) sn_sm[m] = fmaxf(sqrtf(v), 1e-8f);
    }
    __syncthreads();

    float qq = 0.f, d[WAY] = {0.f, 0.f, 0.f, 0.f, 0.f};
    #pragma unroll
    for (int ch = 0; ch < NCHUNK; ch++) {
        const float* pp = g_part + (((size_t)n * NCHUNK + ch) * P + tid) * 8;
        const float4 v0 = *(const float4*)(pp);
        const float4 v1 = *(const float4*)(pp + 4);
        qq += v0.x; d[0] += v0.y; d[1] += v0.z; d[2] += v0.w;
        d[3] += v1.x; d[4] += v1.y;
    }
    const float qn = fmaxf(sqrtf(qq), 1e-8f);

    float sc[WAY], m5 = -1e30f;
    #pragma unroll
    for (int m = 0; m < WAY; m++) {
        sc[m] = 10.0f * d[m] / (qn * sn_sm[m]);
        m5 = fmaxf(m5, sc[m]);
    }
    float se = 0.f;
    #pragma unroll
    for (int m = 0; m < WAY; m++) { sc[m] = __expf(sc[m] - m5); se += sc[m]; }
    const float inv = 1.0f / (se * (float)P);
    #pragma unroll
    for (int m = 0; m < WAY; m++) atomicAdd(&accum[m], sc[m] * inv);
    __syncthreads();
    if (tid < WAY) out[n * WAY + tid] = accum[tid];
}

// ===========================================================================
extern "C" void kernel_launch(void* const* d_in, const int* in_sizes, int n_in,
                              void* d_out, int out_size)
{
    const float* x    = (const float*)d_in[0];
    const float* W    = (const float*)d_in[1];
    const float* bias = (const float*)d_in[2];
    float* out = (float*)d_out;

    zero_kernel<<<1, 256>>>();
    gemm_mma<<<dim3(2, 4, NSAMP), 256>>>(x, W, bias);
    proto_kernel<<<dim3(4, WAY * SHOT), 256>>>(x);
    score_partial_kernel<<<dim3(NCHUNK, NQ), 256>>>(x);
    final_kernel<<<NQ, 256>>>(out);
}

// round 8
// speedup vs baseline: 4.7070x; 1.1790x over previous
#include <cuda_runtime.h>
#include <cuda_fp16.h>
#include <math.h>
#include <stdint.h>

// x: (100, 512, 16, 16) fp32 ; W: (512,512) (outC,inC) ; b: (512,) ; out: (75,5)
#define NSAMP 100
#define C 512
#define P 256
#define ELEMS (C*P)
#define WAY 5
#define SHOT 5
#define NQ 75
#define NCHUNK 4
#define CPERCHUNK 128

__device__ __half g_xh[NSAMP * ELEMS];         // x^T fp16 [b][f][c], 26 MB
__device__ __half g_Wh[C * C];                 // W fp16 [o][c]
__device__ __half g_logits[NSAMP * ELEMS];     // [b][f][c] fp16, 26 MB
__device__ float  g_sum[NSAMP];
__device__ float  g_protoAcc[WAY * C];
__device__ float  g_part[NQ * NCHUNK * P * 8];

// ===========================================================================
__device__ __forceinline__ uint32_t smem_u32(const void* p) {
    uint32_t a;
    asm("{ .reg .u64 t; cvta.to.shared.u64 t, %1; cvt.u32.u64 %0, t; }"
        : "=r"(a) : "l"(p));
    return a;
}
__device__ __forceinline__ void ldsm4(uint32_t (&r)[4], uint32_t addr) {
    asm volatile("ldmatrix.sync.aligned.m8n8.x4.shared.b16 {%0,%1,%2,%3}, [%4];"
                 : "=r"(r[0]), "=r"(r[1]), "=r"(r[2]), "=r"(r[3]) : "r"(addr));
}
__device__ __forceinline__ void mma16816(float (&d)[4], const uint32_t (&a)[4],
                                         uint32_t b0, uint32_t b1) {
    asm volatile(
        "mma.sync.aligned.m16n8k16.row.col.f32.f16.f16.f32 "
        "{%0,%1,%2,%3},{%4,%5,%6,%7},{%8,%9},{%0,%1,%2,%3};"
        : "+f"(d[0]), "+f"(d[1]), "+f"(d[2]), "+f"(d[3])
        : "r"(a[0]), "r"(a[1]), "r"(a[2]), "r"(a[3]), "r"(b0), "r"(b1));
}
__device__ __forceinline__ uint32_t pkh(float a, float b) {
    __half2 h = __floats2half2_rn(a, b);
    return *(uint32_t*)&h;
}
// 16B-chunk XOR swizzle inside a 64B row (4 chunks)
__device__ __forceinline__ int swz(int row, int ch) {
    return row * 64 + ((ch ^ ((row >> 1) & 3)) << 4);
}
__device__ __forceinline__ void cp16(uint32_t dst, const void* src) {
    asm volatile("cp.async.cg.shared.global [%0], [%1], 16;"
                 :: "r"(dst), "l"(src));
}
#define CP_COMMIT() asm volatile("cp.async.commit_group;" ::: "memory")
#define CP_WAIT2()  asm volatile("cp.async.wait_group 2;" ::: "memory")

// ===========================================================================
// K0: convert. b<100: xT fp16 [b][f][c]; b==100: W fp16 (+zero accumulators).
// grid (4, 101), 256 threads.
// ===========================================================================
__global__ __launch_bounds__(256) void conv_kernel(
    const float* __restrict__ x, const float* __restrict__ W)
{
    const int b = blockIdx.y;
    const int f = threadIdx.x;
    if (b < NSAMP) {
        const int c0 = blockIdx.x * 128;
        const float* xb = x + (size_t)b * ELEMS + f;
        __half* dst = g_xh + (size_t)b * ELEMS + (size_t)f * C + c0;
        #pragma unroll
        for (int k = 0; k < 16; k++) {
            const float* sp = xb + (size_t)(c0 + k * 8) * P;
            uint4 u;
            u.x = pkh(sp[0], sp[P]);
            u.y = pkh(sp[2 * P], sp[3 * P]);
            u.z = pkh(sp[4 * P], sp[5 * P]);
            u.w = pkh(sp[6 * P], sp[7 * P]);
            *(uint4*)(dst + k * 8) = u;
        }
    } else {
        const int start = blockIdx.x * 65536;
        #pragma unroll 4
        for (int t = 0; t < 64; t++) {
            const int i4 = start + (t * 256 + threadIdx.x) * 4;
            const float4 v = *(const float4*)(W + i4);
            *(uint2*)(g_Wh + i4) = make_uint2(pkh(v.x, v.y), pkh(v.z, v.w));
        }
        if (blockIdx.x == 0) {
            for (int i = threadIdx.x; i < NSAMP + WAY * C; i += 256) {
                if (i < NSAMP) g_sum[i] = 0.f;
                else g_protoAcc[i - NSAMP] = 0.f;
            }
        }
    }
}

// ===========================================================================
// K1: fp16 mma.sync GEMM, cp.async 4-stage pipeline.
// D[p(128), o(128)] = sum_c xT[p][c] * W[o][c].  BK=32, 8 warps, warp 64x32.
// Stage: A@+0 (8KB), B@+8192 (8KB); 4 stages = 64KB dynamic smem.
// Epilogue: +bias, sum(exp) -> g_sum, fp16 logits [b][f][c] via smem staging.
// ===========================================================================
#define STAGE_PITCH 136   // halves, staging pitch

__global__ __launch_bounds__(256, 2) void gemm_mma(
    const float* __restrict__ bias)
{
    extern __shared__ __align__(128) uint8_t smdyn[];
    __shared__ float sm_red[8];
    __shared__ float sm_bias[128];

    const int b   = blockIdx.z;
    const int p0  = blockIdx.x * 128;
    const int o0  = blockIdx.y * 128;
    const int tid = threadIdx.x;
    const int wid = tid >> 5;
    const int lane = tid & 31;
    const int wm = (wid & 1) * 64;
    const int wn = (wid >> 1) * 32;

    if (tid < 128) sm_bias[tid] = bias[o0 + tid];

    const uint32_t smb = smem_u32(smdyn);

    // cp.async mapping: thread -> (row = tid>>1, 2 chunks of 16B)
    const int rowcp = tid >> 1;
    const int chcp  = (tid & 1) * 2;
    const __half* aSrc = g_xh + (size_t)b * ELEMS + (size_t)(p0 + rowcp) * C + chcp * 8;
    const __half* bSrc = g_Wh + (size_t)(o0 + rowcp) * C + chcp * 8;
    const uint32_t aDst0 = swz(rowcp, chcp),     aDst1 = swz(rowcp, chcp + 1);
    const uint32_t bDst0 = 8192 + aDst0,         bDst1 = 8192 + aDst1;

    // ldmatrix addresses (stage-relative)
    uint32_t aLd[2][4], bLd[2][2];
    #pragma unroll
    for (int ks = 0; ks < 2; ks++) {
        #pragma unroll
        for (int mi = 0; mi < 4; mi++) {
            const int row = wm + mi * 16 + (lane & 15);
            aLd[ks][mi] = smb + swz(row, ks * 2 + (lane >> 4));
        }
        #pragma unroll
        for (int np = 0; np < 2; np++) {
            const int g = lane >> 3;
            const int row = wn + np * 16 + ((g >> 1) << 3) + (lane & 7);
            bLd[ks][np] = smb + 8192 + swz(row, ks * 2 + (g & 1));
        }
    }

    float acc[4][4][4];
    #pragma unroll
    for (int mi = 0; mi < 4; mi++)
        #pragma unroll
        for (int ni = 0; ni < 4; ni++)
            #pragma unroll
            for (int r = 0; r < 4; r++) acc[mi][ni][r] = 0.f;

    // prefetch stages 0..2
    #pragma unroll
    for (int kt = 0; kt < 3; kt++) {
        const uint32_t sb = smb + kt * 16384;
        const __half* as = aSrc + kt * 32;
        const __half* bs = bSrc + kt * 32;
        cp16(sb + aDst0, as); cp16(sb + aDst1, as + 8);
        cp16(sb + bDst0, bs); cp16(sb + bDst1, bs + 8);
        CP_COMMIT();
    }

    for (int kt = 0; kt < 16; kt++) {
        CP_WAIT2();
        __syncthreads();
        if (kt + 3 < 16) {
            const uint32_t sb = smb + ((kt + 3) & 3) * 16384;
            const __half* as = aSrc + (kt + 3) * 32;
            const __half* bs = bSrc + (kt + 3) * 32;
            cp16(sb + aDst0, as); cp16(sb + aDst1, as + 8);
            cp16(sb + bDst0, bs); cp16(sb + bDst1, bs + 8);
        }
        CP_COMMIT();

        const uint32_t stA = (kt & 3) * 16384;
        #pragma unroll
        for (int ks = 0; ks < 2; ks++) {
            uint32_t ar[4][4], br[2][4];
            #pragma unroll
            for (int mi = 0; mi < 4; mi++) ldsm4(ar[mi], aLd[ks][mi] + stA);
            #pragma unroll
            for (int np = 0; np < 2; np++) ldsm4(br[np], bLd[ks][np] + stA);
            #pragma unroll
            for (int mi = 0; mi < 4; mi++)
                #pragma unroll
                for (int ni = 0; ni < 4; ni++)
                    mma16816(acc[mi][ni], ar[mi],
                             br[ni >> 1][(ni & 1) * 2], br[ni >> 1][(ni & 1) * 2 + 1]);
        }
    }
    __syncthreads();   // all MMA reads done -> smem reusable as staging

    // ---- epilogue: bias + exp-sum + fp16 staging ----
    __half* stg = (__half*)smdyn;
    float esum = 0.f;
    #pragma unroll
    for (int mi = 0; mi < 4; mi++) {
        const int r0 = wm + mi * 16 + (lane >> 2);
        #pragma unroll
        for (int ni = 0; ni < 4; ni++) {
            const int cc = wn + ni * 8 + 2 * (lane & 3);
            const float bv0 = sm_bias[cc], bv1 = sm_bias[cc + 1];
            const float v0 = acc[mi][ni][0] + bv0;
            const float v1 = acc[mi][ni][1] + bv1;
            const float v2 = acc[mi][ni][2] + bv0;
            const float v3 = acc[mi][ni][3] + bv1;
            esum += __expf(v0) + __expf(v1) + __expf(v2) + __expf(v3);
            *(__half2*)(stg + (size_t)r0 * STAGE_PITCH + cc) = __floats2half2_rn(v0, v1);
            *(__half2*)(stg + (size_t)(r0 + 8) * STAGE_PITCH + cc) = __floats2half2_rn(v2, v3);
        }
    }
    #pragma unroll
    for (int o = 16; o > 0; o >>= 1) esum += __shfl_xor_sync(0xffffffffu, esum, o);
    if (lane == 0) sm_red[wid] = esum;
    __syncthreads();
    if (tid == 0) {
        float s = 0.f;
        #pragma unroll
        for (int i = 0; i < 8; i++) s += sm_red[i];
        atomicAdd(&g_sum[b], s);
    }

    // coalesced fp16 store: g_logits[b][f=p0+row][c=o0+seg*8 .. +7]
    __half* dst = g_logits + (size_t)b * ELEMS;
    #pragma unroll
    for (int k = 0; k < 8; k++) {
        const int idx = tid + k * 256;
        const int row = idx >> 4;
        const int seg = idx & 15;
        *(uint4*)(dst + (size_t)(p0 + row) * C + o0 + seg * 8) =
            *(const uint4*)(stg + (size_t)row * STAGE_PITCH + seg * 8);
    }
}

// ===========================================================================
// K2: prototypes (support samples). grid (4 c-groups, 25 (way,shot)).
// ===========================================================================
__global__ __launch_bounds__(256) void proto_kernel(const float* __restrict__ x)
{
    const int way = blockIdx.y / SHOT;
    const int sh  = blockIdx.y % SHOT;
    const int b   = way * 20 + sh;
    const int c0  = blockIdx.x * 128;
    const int f    = threadIdx.x;
    const int lane = f & 31;

    __shared__ float acc[128];
    for (int i = threadIdx.x; i < 128; i += 256) acc[i] = 0.f;
    __syncthreads();

    const float inv = 1.0f / g_sum[b];
    const __half* lg = g_logits + (size_t)b * ELEMS + (size_t)f * C + c0;
    const float*  xb = x        + (size_t)b * ELEMS + (size_t)c0 * P + f;

    for (int c8 = 0; c8 < 16; c8++) {
        const uint4 u = *(const uint4*)(lg + c8 * 8);
        #pragma unroll
        for (int t = 0; t < 4; t++) {
            const float2 lf = __half22float2(((const __half2*)&u)[t]);
            const int c = c8 * 8 + t * 2;
            float v0 = xb[(size_t)c * P]       * __expf(lf.x) * inv;
            float v1 = xb[(size_t)(c + 1) * P] * __expf(lf.y) * inv;
            #pragma unroll
            for (int o = 16; o > 0; o >>= 1) {
                v0 += __shfl_xor_sync(0xffffffffu, v0, o);
                v1 += __shfl_xor_sync(0xffffffffu, v1, o);
            }
            if (lane == 0) { atomicAdd(&acc[c], v0); atomicAdd(&acc[c + 1], v1); }
        }
    }
    __syncthreads();
    if (threadIdx.x < 128)
        atomicAdd(&g_protoAcc[way * C + c0 + threadIdx.x], acc[threadIdx.x]);
}

// ===========================================================================
// K3: score partials. grid (4 chunks, 75 queries); thread = pixel f.
// Reads fp16 xT + fp16 logits, both contiguous per thread.
// ===========================================================================
__global__ __launch_bounds__(256) void score_partial_kernel()
{
    const int chunk = blockIdx.x;
    const int n     = blockIdx.y;
    const int way   = n / 15;
    const int b     = way * 20 + SHOT + (n % 15);
    const int tid   = threadIdx.x;
    const int c0    = chunk * CPERCHUNK;

    __shared__ float s_sm[WAY][CPERCHUNK];
    for (int i = tid; i < WAY * CPERCHUNK; i += 256)
        s_sm[i / CPERCHUNK][i % CPERCHUNK] =
            g_protoAcc[(i / CPERCHUNK) * C + c0 + (i % CPERCHUNK)];
    __syncthreads();

    const float inv = 1.0f / g_sum[b];
    const __half* lg = g_logits + (size_t)b * ELEMS + (size_t)tid * C + c0;
    const __half* xh = g_xh     + (size_t)b * ELEMS + (size_t)tid * C + c0;

    float qq = 0.f, d0 = 0.f, d1 = 0.f, d2 = 0.f, d3 = 0.f, d4 = 0.f;
    for (int c8 = 0; c8 < CPERCHUNK / 8; c8++) {
        const uint4 ul = *(const uint4*)(lg + c8 * 8);
        const uint4 ux = *(const uint4*)(xh + c8 * 8);
        #pragma unroll
        for (int t = 0; t < 4; t++) {
            const float2 lf = __half22float2(((const __half2*)&ul)[t]);
            const float2 xf = __half22float2(((const __half2*)&ux)[t]);
            const int c = c8 * 8 + t * 2;
            const float q0 = xf.x * __expf(lf.x) * inv;
            const float q1 = xf.y * __expf(lf.y) * inv;
            qq += q0 * q0 + q1 * q1;
            d0 += q0 * s_sm[0][c] + q1 * s_sm[0][c + 1];
            d1 += q0 * s_sm[1][c] + q1 * s_sm[1][c + 1];
            d2 += q0 * s_sm[2][c] + q1 * s_sm[2][c + 1];
            d3 += q0 * s_sm[3][c] + q1 * s_sm[3][c + 1];
            d4 += q0 * s_sm[4][c] + q1 * s_sm[4][c + 1];
        }
    }
    float* pp = g_part + (((size_t)n * NCHUNK + chunk) * P + tid) * 8;
    *(float4*)(pp)     = make_float4(qq, d0, d1, d2);
    *(float4*)(pp + 4) = make_float4(d3, d4, 0.f, 0.f);
}

// ===========================================================================
// K4: final. 75 blocks; thread = pixel. Cosine, 5-way softmax, spatial mean.
// ===========================================================================
__global__ __launch_bounds__(256) void final_kernel(float* __restrict__ out)
{
    const int n   = blockIdx.x;
    const int tid = threadIdx.x;

    __shared__ float sn_sm[WAY];
    __shared__ float accum[WAY];
    if (tid < WAY) accum[tid] = 0.f;

    if (tid < WAY * 32) {
        const int m = tid >> 5, lane = tid & 31;
        float v = 0.f;
        #pragma unroll
        for (int i = 0; i < C / 32; i++) {
            const float t = g_protoAcc[m * C + lane + i * 32];
            v += t * t;
        }
        #pragma unroll
        for (int o = 16; o > 0; o >>= 1) v += __shfl_xor_sync(0xffffffffu, v, o);
        if (lane == 0) sn_sm[m] = fmaxf(sqrtf(v), 1e-8f);
    }
    __syncthreads();

    float qq = 0.f, d[WAY] = {0.f, 0.f, 0.f, 0.f, 0.f};
    #pragma unroll
    for (int ch = 0; ch < NCHUNK; ch++) {
        const float* pp = g_part + (((size_t)n * NCHUNK + ch) * P + tid) * 8;
        const float4 v0 = *(const float4*)(pp);
        const float4 v1 = *(const float4*)(pp + 4);
        qq += v0.x; d[0] += v0.y; d[1] += v0.z; d[2] += v0.w;
        d[3] += v1.x; d[4] += v1.y;
    }
    const float qn = fmaxf(sqrtf(qq), 1e-8f);

    float sc[WAY], m5 = -1e30f;
    #pragma unroll
    for (int m = 0; m < WAY; m++) {
        sc[m] = 10.0f * d[m] / (qn * sn_sm[m]);
        m5 = fmaxf(m5, sc[m]);
    }
    float se = 0.f;
    #pragma unroll
    for (int m = 0; m < WAY; m++) { sc[m] = __expf(sc[m] - m5); se += sc[m]; }
    const float inv = 1.0f / (se * (float)P);
    #pragma unroll
    for (int m = 0; m < WAY; m++) atomicAdd(&accum[m], sc[m] * inv);
    __syncthreads();
    if (tid < WAY) out[n * WAY + tid] = accum[tid];
}

// ===========================================================================
extern "C" void kernel_launch(void* const* d_in, const int* in_sizes, int n_in,
                              void* d_out, int out_size)
{
    const float* x    = (const float*)d_in[0];
    const float* W    = (const float*)d_in[1];
    const float* bias = (const float*)d_in[2];
    float* out = (float*)d_out;

    cudaFuncSetAttribute(gemm_mma, cudaFuncAttributeMaxDynamicSharedMemorySize, 65536);

    conv_kernel<<<dim3(4, NSAMP + 1), 256>>>(x, W);
    gemm_mma<<<dim3(2, 4, NSAMP), 256, 65536>>>(bias);
    proto_kernel<<<dim3(4, WAY * SHOT), 256>>>(x);
    score_partial_kernel<<<dim3(NCHUNK, NQ), 256>>>();
    final_kernel<<<NQ, 256>>>(out);
}